// round 1
// baseline (speedup 1.0000x reference)
#include <cuda_runtime.h>

#define N_BLOCKS 32
#define M_REAL   64
#define DT       0.01f
#define DIM      (2 * N_BLOCKS + M_REAL)   // 128

// One warp per row (128 floats). Each lane handles one float4 (4 elements).
// Lanes 0..15: complex region (elements 0..63, pairs interleaved (x0,x1)).
// Lanes 16..31: real region (elements 64..127).
__global__ __launch_bounds__(256) void koopman_kernel(
    const float* __restrict__ x,
    const float* __restrict__ L,
    float* __restrict__ out,
    int batch)
{
    int gid  = blockIdx.x * blockDim.x + threadIdx.x;
    int row  = gid >> 5;
    int lane = gid & 31;
    if (row >= batch) return;

    const float4* x4 = reinterpret_cast<const float4*>(x + (size_t)row * DIM);
    float4*       o4 = reinterpret_cast<float4*>(out + (size_t)row * DIM);
    const float*  Lr = L + (size_t)row * DIM;

    float4 xv = x4[lane];
    float4 ov;

    if (lane < 16) {
        // This lane owns complex pairs p = 2*lane and p+1.
        // mu    = L[0 .. 31]   (pair index p)
        // omega = L[32 .. 63]  (pair index p)
        float2 mu = *reinterpret_cast<const float2*>(Lr + 2 * lane);
        float2 om = *reinterpret_cast<const float2*>(Lr + N_BLOCKS + 2 * lane);

        float e0 = __expf(mu.x * DT);
        float e1 = __expf(mu.y * DT);
        float s0, c0, s1, c1;
        __sincosf(om.x * DT, &s0, &c0);
        __sincosf(om.y * DT, &s1, &c1);

        // pair p: (xv.x, xv.y), pair p+1: (xv.z, xv.w)
        ov.x = e0 * (c0 * xv.x - s0 * xv.y);
        ov.y = e0 * (s0 * xv.x + c0 * xv.y);
        ov.z = e1 * (c1 * xv.z - s1 * xv.w);
        ov.w = e1 * (s1 * xv.z + c1 * xv.w);
    } else {
        // Real region: elements 4*lane .. 4*lane+3 (lane in 16..31 -> 64..127)
        float4 lam = *reinterpret_cast<const float4*>(Lr + 4 * lane);
        ov.x = __expf(lam.x * DT) * xv.x;
        ov.y = __expf(lam.y * DT) * xv.y;
        ov.z = __expf(lam.z * DT) * xv.z;
        ov.w = __expf(lam.w * DT) * xv.w;
    }

    o4[lane] = ov;
}

extern "C" void kernel_launch(void* const* d_in, const int* in_sizes, int n_in,
                              void* d_out, int out_size)
{
    const float* x = (const float*)d_in[0];
    const float* L = (const float*)d_in[1];
    float* out     = (float*)d_out;

    int batch = in_sizes[0] / DIM;          // 131072
    int total_threads = batch * 32;         // one warp per row
    int block = 256;
    int grid  = (total_threads + block - 1) / block;

    koopman_kernel<<<grid, block>>>(x, L, out, batch);
}